// round 9
// baseline (speedup 1.0000x reference)
#include <cuda_runtime.h>
#include <cuda_bf16.h>
#include <cstdint>
#include <math.h>

// ---------------------------------------------------------------------------
// Binary CNN fully fused. Round 9: stall-reduction edition.
//  - __launch_bounds__(128, 12): <=42 regs, 12 blocks/SM (75% occ target)
//  - stage C: wp-peeled outer loop, 6 independent h-chains unrolled inside
//  - stage E fused repack (one less __syncthreads)
// Numerics identical to rounds 5-8 (rel_err == 0.0).
// ---------------------------------------------------------------------------

#define EPSBND 1e-5
#define BAND   1e-3f

// preprocessed weights / params
__device__ float    g_w1s[32 * 9];            // sign(w1) as +-1.0f
__device__ double   g_inv1d[32], g_bz1d[32];  // exact BN params (double)
__device__ double   g_b1d[32];                // conv1 bias (double)
__device__ float2   g_p1[32];                 // fp32 fast path (inv, off)
__device__ __align__(16) unsigned g_wb2[64 * 4];   // [c*4+t], t=3 pad
__device__ int2     g_mt2[64];                // (mu, T)
__device__ __align__(16) unsigned g_wb3[128 * 8];  // [c*8 + 2t + j], 6..7 pad
__device__ int2     g_mt3[128];
__device__ __align__(16) unsigned g_wb4[128 * 6 * 4];  // [c*24 + h*4 + j]
__device__ int2     g_mt4[128];
__device__ unsigned g_wfb[10 * 64];           // [o*64+jw]

__device__ __forceinline__ float bnref(float dv, float bias, float inv, float bz) {
    return __fadd_rn(__fmul_rn(__fadd_rn(dv, bias), inv), bz);
}

__device__ void mk_threshold(float b, float g, float be, float m, float v,
                             int2* mt_out)
{
    float inv = __fmul_rn(g, rsqrtf(__fadd_rn(v, 1e-5f)));
    float bz  = __fsub_rn(be, __fmul_rn(m, inv));
    int mu, T;

    if (inv > 0.0f) {
        int lo = -1025, hi = 1025, ans = 1 << 20;
        while (lo <= hi) {
            int mid = lo + ((hi - lo) >> 1);
            if (bnref((float)mid, b, inv, bz) >= 0.0f) { ans = mid; hi = mid - 1; }
            else lo = mid + 1;
        }
        mu = 1; T = ans;
    } else if (inv < 0.0f) {
        int lo = -1025, hi = 1025, ans = -(1 << 20);
        while (lo <= hi) {
            int mid = lo + ((hi - lo) >> 1);
            if (bnref((float)mid, b, inv, bz) >= 0.0f) { ans = mid; lo = mid + 1; }
            else hi = mid - 1;
        }
        mu = -1; T = -ans;
    } else {
        mu = 0; T = (bz >= 0.0f) ? -(1 << 20) : (1 << 20);
    }
    *mt_out = make_int2(mu, T);
}

__global__ void prep_kernel(
    const float* __restrict__ w1, const float* __restrict__ b1,
    const float* __restrict__ w2, const float* __restrict__ b2,
    const float* __restrict__ w3, const float* __restrict__ b3,
    const float* __restrict__ w4, const float* __restrict__ b4,
    const float* __restrict__ g1, const float* __restrict__ be1,
    const float* __restrict__ m1, const float* __restrict__ v1,
    const float* __restrict__ g2, const float* __restrict__ be2,
    const float* __restrict__ m2, const float* __restrict__ v2,
    const float* __restrict__ g3, const float* __restrict__ be3,
    const float* __restrict__ m3, const float* __restrict__ v3,
    const float* __restrict__ g4, const float* __restrict__ be4,
    const float* __restrict__ m4, const float* __restrict__ v4,
    const float* __restrict__ wf)
{
    int u = blockIdx.x * blockDim.x + threadIdx.x;

    if (u < 288) {                       // sign(w1) as +-1.0f
        g_w1s[u] = (w1[u] >= 0.f) ? 1.f : -1.f;
        return;
    }
    u -= 288;
    if (u < 32) {                        // layer-1 BN params (double + fp32 fold)
        int c = u;
        double inv = (double)g1[c] / sqrt((double)v1[c] + EPSBND);
        double bz  = (double)be1[c] - (double)m1[c] * inv;
        g_inv1d[c] = inv;
        g_bz1d[c]  = bz;
        g_b1d[c]   = (double)b1[c];
        g_p1[c]    = make_float2((float)inv, (float)((double)b1[c] * inv + bz));
        return;
    }
    u -= 32;
    if (u < 320) {                       // integer thresholds, layers 2..4
        if (u < 64)       mk_threshold(b2[u], g2[u], be2[u], m2[u], v2[u], &g_mt2[u]);
        else if (u < 192) { int c = u - 64;
                          mk_threshold(b3[c], g3[c], be3[c], m3[c], v3[c], &g_mt3[c]); }
        else              { int c = u - 192;
                          mk_threshold(b4[c], g4[c], be4[c], m4[c], v4[c], &g_mt4[c]); }
        return;
    }
    u -= 320;
    if (u < 256) {                       // wb2: w2 (64,32,1,3), t=3 pad
        int c = u >> 2, t = u & 3;
        unsigned word = 0;
        if (t < 3)
            for (int i = 0; i < 32; i++)
                word |= (unsigned)(w2[c * 96 + i * 3 + t] >= 0.f) << i;
        g_wb2[u] = word;
        return;
    }
    u -= 256;
    if (u < 1024) {                      // wb3: w3 (128,64,1,3), r=6,7 pad
        int c = u >> 3, r = u & 7;
        unsigned word = 0;
        if (r < 6) {
            int t = r >> 1, j = r & 1;
            for (int i = 0; i < 32; i++) {
                int cin = j * 32 + i;
                word |= (unsigned)(w3[c * 192 + cin * 3 + t] >= 0.f) << i;
            }
        }
        g_wb3[u] = word;
        return;
    }
    u -= 1024;
    if (u < 3072) {                      // wb4: w4 (128,128,6,1)
        int c = u / 24, r = u % 24, h = r >> 2, j = r & 3;
        unsigned word = 0;
        for (int i = 0; i < 32; i++) {
            int cin = j * 32 + i;
            word |= (unsigned)(w4[c * 768 + cin * 6 + h] >= 0.f) << i;
        }
        g_wb4[u] = word;
        return;
    }
    u -= 3072;
    if (u < 640) {                       // wfb: wf (10,2048), k = c*16+w
        int o = u / 64, jw = u % 64;
        unsigned word = 0;
        for (int i = 0; i < 32; i++)
            word |= (unsigned)(wf[o * 2048 + jw * 32 + i] >= 0.f) << i;
        g_wfb[u] = word;
    }
}

// Rare exact path: recompute conv1 pooled-pair sign in double from smem.
__device__ __noinline__ bool conv1_slow(const float* __restrict__ row, int L)
{
    double inv1 = g_inv1d[L], bz1 = g_bz1d[L], bb1 = g_b1d[L];
    double s0 = 0.0, s1 = 0.0;
#pragma unroll
    for (int t = 0; t < 9; t++) {
        double w = (double)g_w1s[L * 9 + t];
        s0 = fma(w, (double)row[t],     s0);
        s1 = fma(w, (double)row[t + 2], s1);
    }
    double y0 = (s0 + bb1) * inv1 + bz1;
    double y1 = (s1 + bb1) * inv1 + bz1;
    return (y0 >= 0.0) || (y1 >= 0.0);
}

// ---------------------------------------------------------------------------
// Main fused kernel: 1 block = 1 sample, 128 threads (4 warps).
// ---------------------------------------------------------------------------
__global__ __launch_bounds__(128, 12)
void bcnn_kernel(const float* __restrict__ x, const float* __restrict__ bf,
                 float* __restrict__ out)
{
    const int b   = blockIdx.x;
    const int tid = threadIdx.x;
    const int W   = tid >> 5;     // warp id
    const int L   = tid & 31;     // lane id

    __shared__ __align__(16) float    xs[6 * 136];   // [6][4 | 128 | 4] padded
    __shared__ __align__(16) unsigned b1s[192];
    __shared__ __align__(16) unsigned b2s[384];
    __shared__ __align__(16) unsigned b3s[384];
    __shared__ __align__(16) unsigned masks[128];

    // load sample with zero padding (4 cols each side)
    const float* xb = x + (size_t)b * 768;
    for (int i = tid; i < 768; i += 128) {
        int r = i >> 7, c = i & 127;
        xs[r * 136 + 4 + c] = xb[i];
    }
    if (tid < 48) {
        int r = tid >> 3, j = tid & 7;
        xs[r * 136 + ((j < 4) ? j : (j + 128))] = 0.f;
    }

    // ---- stage A: conv1 + bias + bn + pool(w2) + binarize ----
    float wrf[9];
#pragma unroll
    for (int t = 0; t < 9; t++) wrf[t] = g_w1s[L * 9 + t];
    float2 p1 = g_p1[L];
    __syncthreads();

    for (int pos = W; pos < 192; pos += 4) {
        int h = pos >> 5, wp = pos & 31;
        const float* row = xs + h * 136 + 4 * wp;
        const float4* rv = (const float4*)row;
        float4 v0 = rv[0], v1 = rv[1], v2 = rv[2];
        float s0, s1;
        s0 = wrf[0] * v0.x;
        s0 = __fmaf_rn(wrf[1], v0.y, s0);
        s0 = __fmaf_rn(wrf[2], v0.z, s0);
        s0 = __fmaf_rn(wrf[3], v0.w, s0);
        s0 = __fmaf_rn(wrf[4], v1.x, s0);
        s0 = __fmaf_rn(wrf[5], v1.y, s0);
        s0 = __fmaf_rn(wrf[6], v1.z, s0);
        s0 = __fmaf_rn(wrf[7], v1.w, s0);
        s0 = __fmaf_rn(wrf[8], v2.x, s0);
        s1 = wrf[0] * v0.z;
        s1 = __fmaf_rn(wrf[1], v0.w, s1);
        s1 = __fmaf_rn(wrf[2], v1.x, s1);
        s1 = __fmaf_rn(wrf[3], v1.y, s1);
        s1 = __fmaf_rn(wrf[4], v1.z, s1);
        s1 = __fmaf_rn(wrf[5], v1.w, s1);
        s1 = __fmaf_rn(wrf[6], v2.x, s1);
        s1 = __fmaf_rn(wrf[7], v2.y, s1);
        s1 = __fmaf_rn(wrf[8], v2.z, s1);
        float ym = fmaxf(__fmaf_rn(s0, p1.x, p1.y), __fmaf_rn(s1, p1.x, p1.y));
        bool bit = (ym >= 0.f);
        if (fabsf(ym) < BAND) bit = conv1_slow(row, L);   // rare exact path
        unsigned word = __ballot_sync(0xffffffffu, bit);
        if (L == 0) b1s[pos] = word;
    }
    __syncthreads();

    // ---- stage B: conv2 (64ch, cin 32, kw 3, pad 1), sliding window ----
    {
        int q = W & 1;                 // channel half, c = q*32 + L
        int c = q * 32 + L;
        uint4 wt = *(const uint4*)&g_wb2[c * 4];   // wt.x/y/z = taps 0/1/2
        int2 mt = g_mt2[c];
        int mu = mt.x, T = mt.y;
        int r0 = 3 * (W >> 1);         // pair 0: rows 0-2, pair 1: rows 3-5
        for (int r = r0; r < r0 + 3; r++) {
            const unsigned* rp = b1s + r * 32;
            unsigned Acur = rp[0], Anext = rp[1];
            {   // w = 0 (2 valid taps)
                int s = __popc(Acur ^ wt.y) + __popc(Anext ^ wt.z);
                unsigned word = __ballot_sync(0xffffffffu, mu * (64 - 2 * s) >= T);
                if (L == 0) b2s[r * 64 + q] = word;
            }
#pragma unroll
            for (int w = 1; w <= 30; w++) {
                unsigned Aprev = Acur; Acur = Anext; Anext = rp[w + 1];
                int s = __popc(Aprev ^ wt.x) + __popc(Acur ^ wt.y)
                      + __popc(Anext ^ wt.z);
                unsigned word = __ballot_sync(0xffffffffu, mu * (96 - 2 * s) >= T);
                if (L == 0) b2s[r * 64 + 2 * w + q] = word;
            }
            {   // w = 31 (2 valid taps)
                int s = __popc(Acur ^ wt.x) + __popc(Anext ^ wt.y);
                unsigned word = __ballot_sync(0xffffffffu, mu * (64 - 2 * s) >= T);
                if (L == 0) b2s[r * 64 + 62 + q] = word;
            }
        }
    }
    __syncthreads();

    // ---- stage C: conv3 (128ch, cin 64, kw 3, pad 1) + pool(w2) ----
    // wp peeled at boundaries; 6 independent h-chains unrolled inside.
    {
        int c = tid;                   // warp W owns channels 32W..32W+31
        uint4 wAB = *(const uint4*)&g_wb3[c * 8];      // w00 w01 w10 w11
        uint2 wC  = *(const uint2*)&g_wb3[c * 8 + 4];  // w20 w21
        int2 mt = g_mt3[c];
        int mu = mt.x, T = mt.y;

        // wp = 0: s0 has 2 taps, s1 has 3
#pragma unroll
        for (int h = 0; h < 6; h++) {
            const unsigned* rp = b2s + h * 64;
            uint4 M = *(const uint4*)rp;
            uint2 N = *(const uint2*)(rp + 4);
            int s0 = __popc(M.x ^ wAB.z) + __popc(M.y ^ wAB.w)
                   + __popc(M.z ^ wC.x)  + __popc(M.w ^ wC.y);
            int s1 = __popc(M.x ^ wAB.x) + __popc(M.y ^ wAB.y)
                   + __popc(M.z ^ wAB.z) + __popc(M.w ^ wAB.w)
                   + __popc(N.x ^ wC.x)  + __popc(N.y ^ wC.y);
            int e0 = mu * (128 - 2 * s0), e1 = mu * (192 - 2 * s1);
            unsigned word = __ballot_sync(0xffffffffu, max(e0, e1) >= T);
            if (L == 0) b3s[h * 64 + W] = word;
        }
        // wp = 1..14: interior, no branches
        for (int wp = 1; wp < 15; wp++) {
#pragma unroll
            for (int h = 0; h < 6; h++) {
                const unsigned* rp = b2s + h * 64 + 4 * wp;
                uint4 M = *(const uint4*)rp;
                uint2 P = *(const uint2*)(rp - 2);
                uint2 N = *(const uint2*)(rp + 4);
                int s0 = __popc(P.x ^ wAB.x) + __popc(P.y ^ wAB.y)
                       + __popc(M.x ^ wAB.z) + __popc(M.y ^ wAB.w)
                       + __popc(M.z ^ wC.x)  + __popc(M.w ^ wC.y);
                int s1 = __popc(M.x ^ wAB.x) + __popc(M.y ^ wAB.y)
                       + __popc(M.z ^ wAB.z) + __popc(M.w ^ wAB.w)
                       + __popc(N.x ^ wC.x)  + __popc(N.y ^ wC.y);
                int e0 = mu * (192 - 2 * s0), e1 = mu * (192 - 2 * s1);
                unsigned word = __ballot_sync(0xffffffffu, max(e0, e1) >= T);
                if (L == 0) b3s[(h * 16 + wp) * 4 + W] = word;
            }
        }
        // wp = 15: s0 has 3 taps, s1 has 2
#pragma unroll
        for (int h = 0; h < 6; h++) {
            const unsigned* rp = b2s + h * 64 + 60;
            uint4 M = *(const uint4*)rp;
            uint2 P = *(const uint2*)(rp - 2);
            int s0 = __popc(P.x ^ wAB.x) + __popc(P.y ^ wAB.y)
                   + __popc(M.x ^ wAB.z) + __popc(M.y ^ wAB.w)
                   + __popc(M.z ^ wC.x)  + __popc(M.w ^ wC.y);
            int s1 = __popc(M.x ^ wAB.x) + __popc(M.y ^ wAB.y)
                   + __popc(M.z ^ wAB.z) + __popc(M.w ^ wAB.w);
            int e0 = mu * (192 - 2 * s0), e1 = mu * (128 - 2 * s1);
            unsigned word = __ballot_sync(0xffffffffu, max(e0, e1) >= T);
            if (L == 0) b3s[(h * 16 + 15) * 4 + W] = word;
        }
    }
    __syncthreads();

    // ---- stage D: conv4 (128ch, cin 128, kh 6, no pad), accumulator form ----
    {
        int c = tid;
        int s[16];
#pragma unroll
        for (int w = 0; w < 16; w++) s[w] = 0;
#pragma unroll
        for (int h = 0; h < 6; h++) {
            uint4 wv = *(const uint4*)&g_wb4[c * 24 + h * 4];
#pragma unroll
            for (int w = 0; w < 16; w++) {
                uint4 A = *(const uint4*)&b3s[(h * 16 + w) * 4];
                s[w] += __popc(A.x ^ wv.x) + __popc(A.y ^ wv.y)
                      + __popc(A.z ^ wv.z) + __popc(A.w ^ wv.w);
            }
        }
        int2 mt = g_mt4[c];
        int mu = mt.x, T = mt.y;
        unsigned mask = 0;
#pragma unroll
        for (int w = 0; w < 16; w++)
            mask |= (mu * (768 - 2 * s[w]) >= T) ? (1u << w) : 0u;
        masks[c] = mask;
    }
    __syncthreads();

    // ---- stage E: fused repack + fc (10 x 2048 binary dot) + bf ----
    {
        uint2 mA = *(const uint2*)&masks[2 * L];
        uint2 mB = *(const uint2*)&masks[64 + 2 * L];
        unsigned f0 = mA.x | (mA.y << 16);
        unsigned f1 = mB.x | (mB.y << 16);
        for (int o = W; o < 10; o += 4) {
            int s = __popc(f0 ^ g_wfb[o * 64 + L])
                  + __popc(f1 ^ g_wfb[o * 64 + 32 + L]);
            int tot = __reduce_add_sync(0xffffffffu, s);
            if (L == 0) out[(size_t)b * 10 + o] = (float)(2048 - 2 * tot) + bf[o];
        }
    }
}

extern "C" void kernel_launch(void* const* d_in, const int* in_sizes, int n_in,
                              void* d_out, int out_size)
{
    const float* x   = (const float*)d_in[0];
    const float* w1  = (const float*)d_in[1];
    const float* b1  = (const float*)d_in[2];
    const float* w2  = (const float*)d_in[3];
    const float* b2  = (const float*)d_in[4];
    const float* w3  = (const float*)d_in[5];
    const float* b3  = (const float*)d_in[6];
    const float* w4  = (const float*)d_in[7];
    const float* b4  = (const float*)d_in[8];
    const float* g1  = (const float*)d_in[9];
    const float* be1 = (const float*)d_in[10];
    const float* m1  = (const float*)d_in[11];
    const float* v1  = (const float*)d_in[12];
    const float* g2  = (const float*)d_in[13];
    const float* be2 = (const float*)d_in[14];
    const float* m2  = (const float*)d_in[15];
    const float* v2  = (const float*)d_in[16];
    const float* g3  = (const float*)d_in[17];
    const float* be3 = (const float*)d_in[18];
    const float* m3  = (const float*)d_in[19];
    const float* v3  = (const float*)d_in[20];
    const float* g4  = (const float*)d_in[21];
    const float* be4 = (const float*)d_in[22];
    const float* m4  = (const float*)d_in[23];
    const float* v4  = (const float*)d_in[24];
    const float* wf  = (const float*)d_in[25];
    const float* bf  = (const float*)d_in[26];

    int B = in_sizes[0] / 768;

    prep_kernel<<<22, 256>>>(w1, b1, w2, b2, w3, b3, w4, b4,
                             g1, be1, m1, v1, g2, be2, m2, v2,
                             g3, be3, m3, v3, g4, be4, m4, v4, wf);
    bcnn_kernel<<<B, 128>>>(x, bf, (float*)d_out);
}

// round 10
// speedup vs baseline: 1.0108x; 1.0108x over previous
#include <cuda_runtime.h>
#include <cuda_bf16.h>
#include <cstdint>
#include <math.h>

// ---------------------------------------------------------------------------
// Binary CNN fully fused. Round 10: latency-hiding edition.
//  - stage C: register sliding window, 1 aligned uint4 LDS per output pair,
//    prefetch one iteration ahead (hides LDS latency behind popc work)
//  - thresholds as  mu*s <= K(C)  (K precomputed per channel & tap-count)
//  - stage D: two 8-accumulator passes (loads batch within reg budget)
//  - __launch_bounds__(128, 10): 51-reg budget (MLP > occupancy tradeoff)
// Numerics identical to rounds 5-9 (rel_err == 0.0).
// ---------------------------------------------------------------------------

#define EPSBND 1e-5
#define BAND   1e-3f

// preprocessed weights / params
__device__ float    g_w1s[32 * 9];            // sign(w1) as +-1.0f
__device__ double   g_inv1d[32], g_bz1d[32];  // exact BN params (double)
__device__ double   g_b1d[32];                // conv1 bias (double)
__device__ float2   g_p1[32];                 // fp32 fast path (inv, off)
__device__ __align__(16) unsigned g_wb2[64 * 4];   // [c*4+t], t=3 pad
__device__ int4     g_mtB[64];                // (mu, K96, K64, 0)
__device__ __align__(16) unsigned g_wb3[128 * 8];  // [c*8 + 2t + j], 6..7 pad
__device__ int4     g_mtC[128];               // (mu, K192, K128, 0)
__device__ __align__(16) unsigned g_wb4[128 * 6 * 4];  // [c*24 + h*4 + j]
__device__ int2     g_mtD[128];               // (mu, K768)
__device__ unsigned g_wfb[10 * 64];           // [o*64+jw]

__device__ __forceinline__ float bnref(float dv, float bias, float inv, float bz) {
    return __fadd_rn(__fmul_rn(__fadd_rn(dv, bias), inv), bz);
}

// Integer threshold: bit(d) = (mu*d >= T) matching (bnref(d) >= 0),
// d in [-1025, 1025], chain weakly monotone in d.
__device__ void mk_threshold(float b, float g, float be, float m, float v,
                             int* mu_out, int* T_out)
{
    float inv = __fmul_rn(g, rsqrtf(__fadd_rn(v, 1e-5f)));
    float bz  = __fsub_rn(be, __fmul_rn(m, inv));
    int mu, T;

    if (inv > 0.0f) {
        int lo = -1025, hi = 1025, ans = 1 << 20;
        while (lo <= hi) {
            int mid = lo + ((hi - lo) >> 1);
            if (bnref((float)mid, b, inv, bz) >= 0.0f) { ans = mid; hi = mid - 1; }
            else lo = mid + 1;
        }
        mu = 1; T = ans;
    } else if (inv < 0.0f) {
        int lo = -1025, hi = 1025, ans = -(1 << 20);
        while (lo <= hi) {
            int mid = lo + ((hi - lo) >> 1);
            if (bnref((float)mid, b, inv, bz) >= 0.0f) { ans = mid; lo = mid + 1; }
            else hi = mid - 1;
        }
        mu = -1; T = -ans;
    } else {
        mu = 0; T = (bz >= 0.0f) ? -(1 << 20) : (1 << 20);
    }
    *mu_out = mu; *T_out = T;
}

// K(C): mu*(C-2s) >= T  <=>  mu*s <= (mu*C - T) >> 1  (arithmetic shift = floor)
__device__ __forceinline__ int kval(int mu, int T, int C) {
    return (mu * C - T) >> 1;
}

__global__ void prep_kernel(
    const float* __restrict__ w1, const float* __restrict__ b1,
    const float* __restrict__ w2, const float* __restrict__ b2,
    const float* __restrict__ w3, const float* __restrict__ b3,
    const float* __restrict__ w4, const float* __restrict__ b4,
    const float* __restrict__ g1, const float* __restrict__ be1,
    const float* __restrict__ m1, const float* __restrict__ v1,
    const float* __restrict__ g2, const float* __restrict__ be2,
    const float* __restrict__ m2, const float* __restrict__ v2,
    const float* __restrict__ g3, const float* __restrict__ be3,
    const float* __restrict__ m3, const float* __restrict__ v3,
    const float* __restrict__ g4, const float* __restrict__ be4,
    const float* __restrict__ m4, const float* __restrict__ v4,
    const float* __restrict__ wf)
{
    int u = blockIdx.x * blockDim.x + threadIdx.x;

    if (u < 288) {                       // sign(w1) as +-1.0f
        g_w1s[u] = (w1[u] >= 0.f) ? 1.f : -1.f;
        return;
    }
    u -= 288;
    if (u < 32) {                        // layer-1 BN params (double + fp32 fold)
        int c = u;
        double inv = (double)g1[c] / sqrt((double)v1[c] + EPSBND);
        double bz  = (double)be1[c] - (double)m1[c] * inv;
        g_inv1d[c] = inv;
        g_bz1d[c]  = bz;
        g_b1d[c]   = (double)b1[c];
        g_p1[c]    = make_float2((float)inv, (float)((double)b1[c] * inv + bz));
        return;
    }
    u -= 32;
    if (u < 320) {                       // integer thresholds -> K values
        int mu, T;
        if (u < 64) {
            mk_threshold(b2[u], g2[u], be2[u], m2[u], v2[u], &mu, &T);
            g_mtB[u] = make_int4(mu, kval(mu, T, 96), kval(mu, T, 64), 0);
        } else if (u < 192) {
            int c = u - 64;
            mk_threshold(b3[c], g3[c], be3[c], m3[c], v3[c], &mu, &T);
            g_mtC[c] = make_int4(mu, kval(mu, T, 192), kval(mu, T, 128), 0);
        } else {
            int c = u - 192;
            mk_threshold(b4[c], g4[c], be4[c], m4[c], v4[c], &mu, &T);
            g_mtD[c] = make_int2(mu, kval(mu, T, 768));
        }
        return;
    }
    u -= 320;
    if (u < 256) {                       // wb2: w2 (64,32,1,3), t=3 pad
        int c = u >> 2, t = u & 3;
        unsigned word = 0;
        if (t < 3)
            for (int i = 0; i < 32; i++)
                word |= (unsigned)(w2[c * 96 + i * 3 + t] >= 0.f) << i;
        g_wb2[u] = word;
        return;
    }
    u -= 256;
    if (u < 1024) {                      // wb3: w3 (128,64,1,3), r=6,7 pad
        int c = u >> 3, r = u & 7;
        unsigned word = 0;
        if (r < 6) {
            int t = r >> 1, j = r & 1;
            for (int i = 0; i < 32; i++) {
                int cin = j * 32 + i;
                word |= (unsigned)(w3[c * 192 + cin * 3 + t] >= 0.f) << i;
            }
        }
        g_wb3[u] = word;
        return;
    }
    u -= 1024;
    if (u < 3072) {                      // wb4: w4 (128,128,6,1)
        int c = u / 24, r = u % 24, h = r >> 2, j = r & 3;
        unsigned word = 0;
        for (int i = 0; i < 32; i++) {
            int cin = j * 32 + i;
            word |= (unsigned)(w4[c * 768 + cin * 6 + h] >= 0.f) << i;
        }
        g_wb4[u] = word;
        return;
    }
    u -= 3072;
    if (u < 640) {                       // wfb: wf (10,2048), k = c*16+w
        int o = u / 64, jw = u % 64;
        unsigned word = 0;
        for (int i = 0; i < 32; i++)
            word |= (unsigned)(wf[o * 2048 + jw * 32 + i] >= 0.f) << i;
        g_wfb[u] = word;
    }
}

// Rare exact path: recompute conv1 pooled-pair sign in double from smem.
__device__ __noinline__ bool conv1_slow(const float* __restrict__ row, int L)
{
    double inv1 = g_inv1d[L], bz1 = g_bz1d[L], bb1 = g_b1d[L];
    double s0 = 0.0, s1 = 0.0;
#pragma unroll
    for (int t = 0; t < 9; t++) {
        double w = (double)g_w1s[L * 9 + t];
        s0 = fma(w, (double)row[t],     s0);
        s1 = fma(w, (double)row[t + 2], s1);
    }
    double y0 = (s0 + bb1) * inv1 + bz1;
    double y1 = (s1 + bb1) * inv1 + bz1;
    return (y0 >= 0.0) || (y1 >= 0.0);
}

// ---------------------------------------------------------------------------
// Main fused kernel: 1 block = 1 sample, 128 threads (4 warps).
// ---------------------------------------------------------------------------
__global__ __launch_bounds__(128, 10)
void bcnn_kernel(const float* __restrict__ x, const float* __restrict__ bf,
                 float* __restrict__ out)
{
    const int b   = blockIdx.x;
    const int tid = threadIdx.x;
    const int W   = tid >> 5;     // warp id
    const int L   = tid & 31;     // lane id

    __shared__ __align__(16) float    xs[6 * 136];   // [6][4 | 128 | 4] padded
    __shared__ __align__(16) unsigned b1s[192];
    // b2s rows of 68 words: word k of row r at [r*68 + 2 + k]; 2-word lead pad
    // makes the stage-C steady-state uint4 load 16B-aligned. Tail pad words
    // (k=64,65) may be read (prefetch) but are never used.
    __shared__ __align__(16) unsigned b2s[6 * 68];
    __shared__ __align__(16) unsigned b3s[384];
    __shared__ __align__(16) unsigned masks[128];

    // load sample with zero padding (4 cols each side)
    const float* xb = x + (size_t)b * 768;
    for (int i = tid; i < 768; i += 128) {
        int r = i >> 7, c = i & 127;
        xs[r * 136 + 4 + c] = xb[i];
    }
    if (tid < 48) {
        int r = tid >> 3, j = tid & 7;
        xs[r * 136 + ((j < 4) ? j : (j + 128))] = 0.f;
    }

    // ---- stage A: conv1 + bias + bn + pool(w2) + binarize ----
    float wrf[9];
#pragma unroll
    for (int t = 0; t < 9; t++) wrf[t] = g_w1s[L * 9 + t];
    float2 p1 = g_p1[L];
    __syncthreads();

    for (int pos = W; pos < 192; pos += 4) {
        int h = pos >> 5, wp = pos & 31;
        const float* row = xs + h * 136 + 4 * wp;
        const float4* rv = (const float4*)row;
        float4 v0 = rv[0], v1 = rv[1], v2 = rv[2];
        float s0, s1;
        s0 = wrf[0] * v0.x;
        s0 = __fmaf_rn(wrf[1], v0.y, s0);
        s0 = __fmaf_rn(wrf[2], v0.z, s0);
        s0 = __fmaf_rn(wrf[3], v0.w, s0);
        s0 = __fmaf_rn(wrf[4], v1.x, s0);
        s0 = __fmaf_rn(wrf[5], v1.y, s0);
        s0 = __fmaf_rn(wrf[6], v1.z, s0);
        s0 = __fmaf_rn(wrf[7], v1.w, s0);
        s0 = __fmaf_rn(wrf[8], v2.x, s0);
        s1 = wrf[0] * v0.z;
        s1 = __fmaf_rn(wrf[1], v0.w, s1);
        s1 = __fmaf_rn(wrf[2], v1.x, s1);
        s1 = __fmaf_rn(wrf[3], v1.y, s1);
        s1 = __fmaf_rn(wrf[4], v1.z, s1);
        s1 = __fmaf_rn(wrf[5], v1.w, s1);
        s1 = __fmaf_rn(wrf[6], v2.x, s1);
        s1 = __fmaf_rn(wrf[7], v2.y, s1);
        s1 = __fmaf_rn(wrf[8], v2.z, s1);
        float ym = fmaxf(__fmaf_rn(s0, p1.x, p1.y), __fmaf_rn(s1, p1.x, p1.y));
        bool bit = (ym >= 0.f);
        if (fabsf(ym) < BAND) bit = conv1_slow(row, L);   // rare exact path
        unsigned word = __ballot_sync(0xffffffffu, bit);
        if (L == 0) b1s[pos] = word;
    }
    __syncthreads();

    // ---- stage B: conv2 (64ch, cin 32, kw 3, pad 1), sliding window ----
    {
        int q = W & 1;                 // channel half, c = q*32 + L
        int c = q * 32 + L;
        uint4 wt = *(const uint4*)&g_wb2[c * 4];   // wt.x/y/z = taps 0/1/2
        int4 mt = g_mtB[c];
        int mu = mt.x, K96 = mt.y, K64 = mt.z;
        int r0 = 3 * (W >> 1);         // pair 0: rows 0-2, pair 1: rows 3-5
        for (int r = r0; r < r0 + 3; r++) {
            const unsigned* rp = b1s + r * 32;
            unsigned* op = b2s + r * 68 + 2 + q;
            unsigned Acur = rp[0], Anext = rp[1];
            {   // w = 0 (2 valid taps)
                int s = __popc(Acur ^ wt.y) + __popc(Anext ^ wt.z);
                unsigned word = __ballot_sync(0xffffffffu, mu * s <= K64);
                if (L == 0) op[0] = word;
            }
#pragma unroll
            for (int w = 1; w <= 30; w++) {
                unsigned Aprev = Acur; Acur = Anext; Anext = rp[w + 1];
                int s = __popc(Aprev ^ wt.x) + __popc(Acur ^ wt.y)
                      + __popc(Anext ^ wt.z);
                unsigned word = __ballot_sync(0xffffffffu, mu * s <= K96);
                if (L == 0) op[2 * w] = word;
            }
            {   // w = 31 (2 valid taps)
                int s = __popc(Acur ^ wt.x) + __popc(Anext ^ wt.y);
                unsigned word = __ballot_sync(0xffffffffu, mu * s <= K64);
                if (L == 0) op[62] = word;
            }
        }
    }
    __syncthreads();

    // ---- stage C: conv3 (128ch, cin 64, kw 3, pad 1) + pool(w2) ----
    // Register sliding window Wd[0..7] = words 4wp-2 .. 4wp+5 of the row;
    // Wd[8..11] prefetch next 4 words (1 aligned uint4 per wp).
    {
        int c = tid;                   // warp W owns channels 32W..32W+31
        uint4 wAB = *(const uint4*)&g_wb3[c * 8];      // w00 w01 w10 w11
        uint2 wC  = *(const uint2*)&g_wb3[c * 8 + 4];  // w20 w21
        int4 mt = g_mtC[c];
        int mu = mt.x, K192 = mt.y, K128 = mt.z;

        for (int h = 0; h < 6; h++) {
            const unsigned* rp2 = b2s + h * 68 + 2;    // word k at rp2[k]
            unsigned Wd[12];
            // wp = 0: window words 0..5 in Wd[2..7]
            {
                uint2 a = *(const uint2*)(rp2 + 0);    // words 0,1
                uint4 bq = *(const uint4*)(rp2 + 2);   // words 2..5 (16B aligned)
                Wd[2] = a.x;  Wd[3] = a.y;
                Wd[4] = bq.x; Wd[5] = bq.y; Wd[6] = bq.z; Wd[7] = bq.w;
            }
            {   // prefetch words 6..9
                uint4 p = *(const uint4*)(rp2 + 6);
                Wd[8] = p.x; Wd[9] = p.y; Wd[10] = p.z; Wd[11] = p.w;
            }
            {   // compute wp = 0 (s0: taps 1,2 only -> K128; s1 full -> K192)
                int s0 = __popc(Wd[2] ^ wAB.z) + __popc(Wd[3] ^ wAB.w)
                       + __popc(Wd[4] ^ wC.x)  + __popc(Wd[5] ^ wC.y);
                int s1 = __popc(Wd[2] ^ wAB.x) + __popc(Wd[3] ^ wAB.y)
                       + __popc(Wd[4] ^ wAB.z) + __popc(Wd[5] ^ wAB.w)
                       + __popc(Wd[6] ^ wC.x)  + __popc(Wd[7] ^ wC.y);
                bool bit = (mu * s0 <= K128) || (mu * s1 <= K192);
                unsigned word = __ballot_sync(0xffffffffu, bit);
                if (L == 0) b3s[h * 64 + W] = word;
            }
#pragma unroll
            for (int i = 0; i < 8; i++) Wd[i] = Wd[i + 4];

#pragma unroll
            for (int wp = 1; wp < 15; wp++) {
                // prefetch words 4wp+6 .. 4wp+9 (16B aligned; wp=14 reads the
                // 2 tail pad words -- loaded but never used)
                uint4 p = *(const uint4*)(rp2 + 4 * wp + 6);
                Wd[8] = p.x; Wd[9] = p.y; Wd[10] = p.z; Wd[11] = p.w;
                int s0 = __popc(Wd[0] ^ wAB.x) + __popc(Wd[1] ^ wAB.y)
                       + __popc(Wd[2] ^ wAB.z) + __popc(Wd[3] ^ wAB.w)
                       + __popc(Wd[4] ^ wC.x)  + __popc(Wd[5] ^ wC.y);
                int s1 = __popc(Wd[2] ^ wAB.x) + __popc(Wd[3] ^ wAB.y)
                       + __popc(Wd[4] ^ wAB.z) + __popc(Wd[5] ^ wAB.w)
                       + __popc(Wd[6] ^ wC.x)  + __popc(Wd[7] ^ wC.y);
                bool bit = (mu * s0 <= K192) || (mu * s1 <= K192);
                unsigned word = __ballot_sync(0xffffffffu, bit);
                if (L == 0) b3s[h * 64 + wp * 4 + W] = word;
#pragma unroll
                for (int i = 0; i < 8; i++) Wd[i] = Wd[i + 4];
            }
            {   // wp = 15 (s0 full -> K192; s1: taps 0,1 only -> K128)
                int s0 = __popc(Wd[0] ^ wAB.x) + __popc(Wd[1] ^ wAB.y)
                       + __popc(Wd[2] ^ wAB.z) + __popc(Wd[3] ^ wAB.w)
                       + __popc(Wd[4] ^ wC.x)  + __popc(Wd[5] ^ wC.y);
                int s1 = __popc(Wd[2] ^ wAB.x) + __popc(Wd[3] ^ wAB.y)
                       + __popc(Wd[4] ^ wAB.z) + __popc(Wd[5] ^ wAB.w);
                bool bit = (mu * s0 <= K192) || (mu * s1 <= K128);
                unsigned word = __ballot_sync(0xffffffffu, bit);
                if (L == 0) b3s[h * 64 + 60 + W] = word;
            }
        }
    }
    __syncthreads();

    // ---- stage D: conv4 (128ch, cin 128, kh 6, no pad), 2x8 accumulators ----
    {
        int c = tid;
        int2 mt = g_mtD[c];
        int mu = mt.x, K = mt.y;
        unsigned mask = 0;
#pragma unroll
        for (int pass = 0; pass < 2; pass++) {
            int s[8];
#pragma unroll
            for (int w = 0; w < 8; w++) s[w] = 0;
#pragma unroll
            for (int h = 0; h < 6; h++) {
                uint4 wv = *(const uint4*)&g_wb4[c * 24 + h * 4];
#pragma unroll
                for (int w = 0; w < 8; w++) {
                    uint4 A = *(const uint4*)&b3s[(h * 16 + pass * 8 + w) * 4];
                    s[w] += __popc(A.x ^ wv.x) + __popc(A.y ^ wv.y)
                          + __popc(A.z ^ wv.z) + __popc(A.w ^ wv.w);
                }
            }
#pragma unroll
            for (int w = 0; w < 8; w++)
                mask |= (mu * s[w] <= K) ? (1u << (pass * 8 + w)) : 0u;
        }
        masks[c] = mask;
    }
    __syncthreads();

    // ---- stage E: fused repack + fc (10 x 2048 binary dot) + bf ----
    {
        uint2 mA = *(const uint2*)&masks[2 * L];
        uint2 mB = *(const uint2*)&masks[64 + 2 * L];
        unsigned f0 = mA.x | (mA.y << 16);
        unsigned f1 = mB.x | (mB.y << 16);
        for (int o = W; o < 10; o += 4) {
            int s = __popc(f0 ^ g_wfb[o * 64 + L])
                  + __popc(f1 ^ g_wfb[o * 64 + 32 + L]);
            int tot = __reduce_add_sync(0xffffffffu, s);
            if (L == 0) out[(size_t)b * 10 + o] = (float)(2048 - 2 * tot) + bf[o];
        }
    }
}

extern "C" void kernel_launch(void* const* d_in, const int* in_sizes, int n_in,
                              void* d_out, int out_size)
{
    const float* x   = (const float*)d_in[0];
    const float* w1  = (const float*)d_in[1];
    const float* b1  = (const float*)d_in[2];
    const float* w2  = (const float*)d_in[3];
    const float* b2  = (const float*)d_in[4];
    const float* w3  = (const float*)d_in[5];
    const float* b3  = (const float*)d_in[6];
    const float* w4  = (const float*)d_in[7];
    const float* b4  = (const float*)d_in[8];
    const float* g1  = (const float*)d_in[9];
    const float* be1 = (const float*)d_in[10];
    const float* m1  = (const float*)d_in[11];
    const float* v1  = (const float*)d_in[12];
    const float* g2  = (const float*)d_in[13];
    const float* be2 = (const float*)d_in[14];
    const float* m2  = (const float*)d_in[15];
    const float* v2  = (const float*)d_in[16];
    const float* g3  = (const float*)d_in[17];
    const float* be3 = (const float*)d_in[18];
    const float* m3  = (const float*)d_in[19];
    const float* v3  = (const float*)d_in[20];
    const float* g4  = (const float*)d_in[21];
    const float* be4 = (const float*)d_in[22];
    const float* m4  = (const float*)d_in[23];
    const float* v4  = (const float*)d_in[24];
    const float* wf  = (const float*)d_in[25];
    const float* bf  = (const float*)d_in[26];

    int B = in_sizes[0] / 768;

    prep_kernel<<<22, 256>>>(w1, b1, w2, b2, w3, b3, w4, b4,
                             g1, be1, m1, v1, g2, be2, m2, v2,
                             g3, be3, m3, v3, g4, be4, m4, v4, wf);
    bcnn_kernel<<<B, 128>>>(x, bf, (float*)d_out);
}

// round 11
// speedup vs baseline: 1.0188x; 1.0079x over previous
#include <cuda_runtime.h>
#include <cuda_bf16.h>
#include <cstdint>
#include <math.h>

// ---------------------------------------------------------------------------
// Binary CNN fully fused. Round 11: divergence/wavefront purge.
//  - all-lanes same-address STS for ballot results (no BSSY/BSYNC per output)
//  - complement-weight trick: per-channel sign folded into weight bits at prep
//    (sign(inv)=sign(g)); runtime test is uniform  s <= K  (no mu IMAD)
//  - stage B: quad sliding window, 8 aligned LDS.128 per row (was 32 LDS.32)
//  - stage D: weights transposed to [h*4+j][c] -> coalesced LDG.32
// Numerics identical to rounds 5-10 (rel_err == 0.0).
// ---------------------------------------------------------------------------

#define EPSBND 1e-5
#define BAND   1e-3f

// preprocessed weights / params
__device__ float    g_w1s[32 * 9];            // sign(w1) as +-1.0f
__device__ double   g_inv1d[32], g_bz1d[32];  // exact BN params (double)
__device__ double   g_b1d[32];                // conv1 bias (double)
__device__ float2   g_p1[32];                 // fp32 fast path (inv, off)
__device__ __align__(16) unsigned g_wb2[64 * 4];   // [c*4+t], t=3 pad (sign-folded)
__device__ int2     g_kB[64];                 // (K96, K64)
__device__ __align__(16) unsigned g_wb3[128 * 8];  // [c*8 + 2t + j] (sign-folded)
__device__ int2     g_kC[128];                // (K192, K128)
__device__ unsigned g_wb4t[24 * 128];         // [(h*4+j)*128 + c] (sign-folded)
__device__ int      g_kD[128];                // K768
__device__ unsigned g_wfb[10 * 64];           // [o*64+jw]

__device__ __forceinline__ float bnref(float dv, float bias, float inv, float bz) {
    return __fadd_rn(__fmul_rn(__fadd_rn(dv, bias), inv), bz);
}

// Compute K values: with (possibly sign-folded) weights, output bit == (s <= K(C)),
// where s = sum of popc(A ^ W) over the C/32 words, exactly matching
// (bnref(C - 2*s_orig) >= 0) for the reference fp32 BN chain.
__device__ void mk_k(float b, float g, float be, float m, float v,
                     int C0, int C1, int* K0, int* K1)
{
    float inv = __fmul_rn(g, rsqrtf(__fadd_rn(v, 1e-5f)));
    float bz  = __fsub_rn(be, __fmul_rn(m, inv));

    if (inv > 0.0f) {                    // bit <=> d >= d*  <=> s <= (C - d*)/2
        int lo = -1025, hi = 1025, ans = 1 << 20;
        while (lo <= hi) {
            int mid = lo + ((hi - lo) >> 1);
            if (bnref((float)mid, b, inv, bz) >= 0.0f) { ans = mid; hi = mid - 1; }
            else lo = mid + 1;
        }
        *K0 = (C0 - ans) >> 1;
        *K1 = (C1 - ans) >> 1;
    } else if (inv < 0.0f) {             // weights complemented: s' = C - s
        // bit <=> d <= A  <=> s >= (C-A)/2  <=> s' <= (C + A)/2
        int lo = -1025, hi = 1025, ans = -(1 << 20);
        while (lo <= hi) {
            int mid = lo + ((hi - lo) >> 1);
            if (bnref((float)mid, b, inv, bz) >= 0.0f) { ans = mid; lo = mid + 1; }
            else hi = mid - 1;
        }
        *K0 = (C0 + ans) >> 1;
        *K1 = (C1 + ans) >> 1;
    } else {                             // constant
        bool always = (bz >= 0.0f);
        *K0 = always ? C0 : -1;
        *K1 = always ? C1 : -1;
    }
}

__global__ void prep_kernel(
    const float* __restrict__ w1, const float* __restrict__ b1,
    const float* __restrict__ w2, const float* __restrict__ b2,
    const float* __restrict__ w3, const float* __restrict__ b3,
    const float* __restrict__ w4, const float* __restrict__ b4,
    const float* __restrict__ g1, const float* __restrict__ be1,
    const float* __restrict__ m1, const float* __restrict__ v1,
    const float* __restrict__ g2, const float* __restrict__ be2,
    const float* __restrict__ m2, const float* __restrict__ v2,
    const float* __restrict__ g3, const float* __restrict__ be3,
    const float* __restrict__ m3, const float* __restrict__ v3,
    const float* __restrict__ g4, const float* __restrict__ be4,
    const float* __restrict__ m4, const float* __restrict__ v4,
    const float* __restrict__ wf)
{
    int u = blockIdx.x * blockDim.x + threadIdx.x;

    if (u < 288) {                       // sign(w1) as +-1.0f
        g_w1s[u] = (w1[u] >= 0.f) ? 1.f : -1.f;
        return;
    }
    u -= 288;
    if (u < 32) {                        // layer-1 BN params (double + fp32 fold)
        int c = u;
        double inv = (double)g1[c] / sqrt((double)v1[c] + EPSBND);
        double bz  = (double)be1[c] - (double)m1[c] * inv;
        g_inv1d[c] = inv;
        g_bz1d[c]  = bz;
        g_b1d[c]   = (double)b1[c];
        g_p1[c]    = make_float2((float)inv, (float)((double)b1[c] * inv + bz));
        return;
    }
    u -= 32;
    if (u < 320) {                       // K thresholds, layers 2..4
        if (u < 64) {
            int K0, K1;
            mk_k(b2[u], g2[u], be2[u], m2[u], v2[u], 96, 64, &K0, &K1);
            g_kB[u] = make_int2(K0, K1);
        } else if (u < 192) {
            int c = u - 64, K0, K1;
            mk_k(b3[c], g3[c], be3[c], m3[c], v3[c], 192, 128, &K0, &K1);
            g_kC[c] = make_int2(K0, K1);
        } else {
            int c = u - 192, K0, K1;
            mk_k(b4[c], g4[c], be4[c], m4[c], v4[c], 768, 768, &K0, &K1);
            g_kD[c] = K0;
        }
        return;
    }
    u -= 320;
    if (u < 256) {                       // wb2: w2 (64,32,1,3), t=3 pad, sign-folded
        int c = u >> 2, t = u & 3;
        unsigned flip = (g2[c] < 0.f) ? 0xffffffffu : 0u;
        unsigned word = 0;
        if (t < 3) {
            for (int i = 0; i < 32; i++)
                word |= (unsigned)(w2[c * 96 + i * 3 + t] >= 0.f) << i;
            word ^= flip;
        }
        g_wb2[u] = word;
        return;
    }
    u -= 256;
    if (u < 1024) {                      // wb3: w3 (128,64,1,3), r=6,7 pad, sign-folded
        int c = u >> 3, r = u & 7;
        unsigned flip = (g3[c] < 0.f) ? 0xffffffffu : 0u;
        unsigned word = 0;
        if (r < 6) {
            int t = r >> 1, j = r & 1;
            for (int i = 0; i < 32; i++) {
                int cin = j * 32 + i;
                word |= (unsigned)(w3[c * 192 + cin * 3 + t] >= 0.f) << i;
            }
            word ^= flip;
        }
        g_wb3[u] = word;
        return;
    }
    u -= 1024;
    if (u < 3072) {                      // wb4t: w4 (128,128,6,1), transposed + folded
        int c = u / 24, r = u % 24, h = r >> 2, j = r & 3;
        unsigned flip = (g4[c] < 0.f) ? 0xffffffffu : 0u;
        unsigned word = 0;
        for (int i = 0; i < 32; i++) {
            int cin = j * 32 + i;
            word |= (unsigned)(w4[c * 768 + cin * 6 + h] >= 0.f) << i;
        }
        g_wb4t[(h * 4 + j) * 128 + c] = word ^ flip;
        return;
    }
    u -= 3072;
    if (u < 640) {                       // wfb: wf (10,2048), k = c*16+w
        int o = u / 64, jw = u % 64;
        unsigned word = 0;
        for (int i = 0; i < 32; i++)
            word |= (unsigned)(wf[o * 2048 + jw * 32 + i] >= 0.f) << i;
        g_wfb[u] = word;
    }
}

// Rare exact path: recompute conv1 pooled-pair sign in double from smem.
__device__ __noinline__ bool conv1_slow(const float* __restrict__ row, int L)
{
    double inv1 = g_inv1d[L], bz1 = g_bz1d[L], bb1 = g_b1d[L];
    double s0 = 0.0, s1 = 0.0;
#pragma unroll
    for (int t = 0; t < 9; t++) {
        double w = (double)g_w1s[L * 9 + t];
        s0 = fma(w, (double)row[t],     s0);
        s1 = fma(w, (double)row[t + 2], s1);
    }
    double y0 = (s0 + bb1) * inv1 + bz1;
    double y1 = (s1 + bb1) * inv1 + bz1;
    return (y0 >= 0.0) || (y1 >= 0.0);
}

// ---------------------------------------------------------------------------
// Main fused kernel: 1 block = 1 sample, 128 threads (4 warps).
// ---------------------------------------------------------------------------
__global__ __launch_bounds__(128, 10)
void bcnn_kernel(const float* __restrict__ x, const float* __restrict__ bf,
                 float* __restrict__ out)
{
    const int b   = blockIdx.x;
    const int tid = threadIdx.x;
    const int W   = tid >> 5;     // warp id
    const int L   = tid & 31;     // lane id

    __shared__ __align__(16) float    xs[6 * 136];   // [6][4 | 128 | 4] padded
    __shared__ __align__(16) unsigned b1s[192];
    // b2s rows of 68 words: word k of row r at [r*68 + 2 + k]; 2-word lead pad
    // aligns stage-C steady-state uint4 loads; tail pad absorbs prefetch.
    __shared__ __align__(16) unsigned b2s[6 * 68];
    __shared__ __align__(16) unsigned b3s[384];
    __shared__ __align__(16) unsigned masks[128];

    // load sample with zero padding (4 cols each side)
    const float* xb = x + (size_t)b * 768;
    for (int i = tid; i < 768; i += 128) {
        int r = i >> 7, c = i & 127;
        xs[r * 136 + 4 + c] = xb[i];
    }
    if (tid < 48) {
        int r = tid >> 3, j = tid & 7;
        xs[r * 136 + ((j < 4) ? j : (j + 128))] = 0.f;
    }

    // ---- stage A: conv1 + bias + bn + pool(w2) + binarize ----
    float wrf[9];
#pragma unroll
    for (int t = 0; t < 9; t++) wrf[t] = g_w1s[L * 9 + t];
    float2 p1 = g_p1[L];
    __syncthreads();

    for (int pos = W; pos < 192; pos += 4) {
        int h = pos >> 5, wp = pos & 31;
        const float* row = xs + h * 136 + 4 * wp;
        const float4* rv = (const float4*)row;
        float4 v0 = rv[0], v1 = rv[1], v2 = rv[2];
        float s0, s1;
        s0 = wrf[0] * v0.x;
        s0 = __fmaf_rn(wrf[1], v0.y, s0);
        s0 = __fmaf_rn(wrf[2], v0.z, s0);
        s0 = __fmaf_rn(wrf[3], v0.w, s0);
        s0 = __fmaf_rn(wrf[4], v1.x, s0);
        s0 = __fmaf_rn(wrf[5], v1.y, s0);
        s0 = __fmaf_rn(wrf[6], v1.z, s0);
        s0 = __fmaf_rn(wrf[7], v1.w, s0);
        s0 = __fmaf_rn(wrf[8], v2.x, s0);
        s1 = wrf[0] * v0.z;
        s1 = __fmaf_rn(wrf[1], v0.w, s1);
        s1 = __fmaf_rn(wrf[2], v1.x, s1);
        s1 = __fmaf_rn(wrf[3], v1.y, s1);
        s1 = __fmaf_rn(wrf[4], v1.z, s1);
        s1 = __fmaf_rn(wrf[5], v1.w, s1);
        s1 = __fmaf_rn(wrf[6], v2.x, s1);
        s1 = __fmaf_rn(wrf[7], v2.y, s1);
        s1 = __fmaf_rn(wrf[8], v2.z, s1);
        float ym = fmaxf(__fmaf_rn(s0, p1.x, p1.y), __fmaf_rn(s1, p1.x, p1.y));
        bool bit = (ym >= 0.f);
        if (fabsf(ym) < BAND) bit = conv1_slow(row, L);   // rare exact path
        b1s[pos] = __ballot_sync(0xffffffffu, bit);       // all-lanes store
    }
    __syncthreads();

    // ---- stage B: conv2 (64ch, cin 32, kw 3, pad 1), quad sliding window ----
    {
        int q = W & 1;                 // channel half, c = q*32 + L
        int c = q * 32 + L;
        uint4 wt = *(const uint4*)&g_wb2[c * 4];   // taps 0/1/2 (sign-folded)
        int2 kb = g_kB[c];
        int K96 = kb.x, K64 = kb.y;
        int r0 = 3 * (W >> 1);         // pair 0: rows 0-2, pair 1: rows 3-5
        for (int r = r0; r < r0 + 3; r++) {
            const unsigned* rp = b1s + r * 32;
            unsigned* op = b2s + r * 68 + 2 + q;
            uint4 A = *(const uint4*)rp;           // words 0..3
            // w = 0 (taps 1,2 on words 0,1)
            {
                int s = __popc(A.x ^ wt.y) + __popc(A.y ^ wt.z);
                op[0] = __ballot_sync(0xffffffffu, s <= K64);
            }
            // w = 1, 2
            {
                int s = __popc(A.x ^ wt.x) + __popc(A.y ^ wt.y) + __popc(A.z ^ wt.z);
                op[2] = __ballot_sync(0xffffffffu, s <= K96);
            }
            {
                int s = __popc(A.y ^ wt.x) + __popc(A.z ^ wt.y) + __popc(A.w ^ wt.z);
                op[4] = __ballot_sync(0xffffffffu, s <= K96);
            }
            unsigned p2 = A.z, p3 = A.w;
#pragma unroll
            for (int k = 1; k < 8; k++) {
                A = *(const uint4*)(rp + 4 * k);   // words 4k..4k+3
                int s;
                s = __popc(p2 ^ wt.x) + __popc(p3 ^ wt.y) + __popc(A.x ^ wt.z);
                op[2 * (4 * k - 1)] = __ballot_sync(0xffffffffu, s <= K96);
                s = __popc(p3 ^ wt.x) + __popc(A.x ^ wt.y) + __popc(A.y ^ wt.z);
                op[2 * (4 * k)]     = __ballot_sync(0xffffffffu, s <= K96);
                s = __popc(A.x ^ wt.x) + __popc(A.y ^ wt.y) + __popc(A.z ^ wt.z);
                op[2 * (4 * k + 1)] = __ballot_sync(0xffffffffu, s <= K96);
                s = __popc(A.y ^ wt.x) + __popc(A.z ^ wt.y) + __popc(A.w ^ wt.z);
                op[2 * (4 * k + 2)] = __ballot_sync(0xffffffffu, s <= K96);
                p2 = A.z; p3 = A.w;
            }
            // w = 31 (taps 0,1 on words 30,31)
            {
                int s = __popc(p2 ^ wt.x) + __popc(p3 ^ wt.y);
                op[62] = __ballot_sync(0xffffffffu, s <= K64);
            }
        }
    }
    __syncthreads();

    // ---- stage C: conv3 (128ch, cin 64, kw 3, pad 1) + pool(w2) ----
    // Register sliding window, 1 aligned uint4 prefetch per wp.
    {
        int c = tid;                   // warp W owns channels 32W..32W+31
        uint4 wAB = *(const uint4*)&g_wb3[c * 8];      // w00 w01 w10 w11
        uint2 wC  = *(const uint2*)&g_wb3[c * 8 + 4];  // w20 w21
        int2 kc = g_kC[c];
        int K192 = kc.x, K128 = kc.y;

        for (int h = 0; h < 6; h++) {
            const unsigned* rp2 = b2s + h * 68 + 2;    // word k at rp2[k]
            unsigned Wd[12];
            {
                uint2 a = *(const uint2*)(rp2 + 0);
                uint4 bq = *(const uint4*)(rp2 + 2);
                Wd[2] = a.x;  Wd[3] = a.y;
                Wd[4] = bq.x; Wd[5] = bq.y; Wd[6] = bq.z; Wd[7] = bq.w;
            }
            {
                uint4 p = *(const uint4*)(rp2 + 6);
                Wd[8] = p.x; Wd[9] = p.y; Wd[10] = p.z; Wd[11] = p.w;
            }
            {   // wp = 0 (s0: taps 1,2 -> K128; s1 full -> K192)
                int s0 = __popc(Wd[2] ^ wAB.z) + __popc(Wd[3] ^ wAB.w)
                       + __popc(Wd[4] ^ wC.x)  + __popc(Wd[5] ^ wC.y);
                int s1 = __popc(Wd[2] ^ wAB.x) + __popc(Wd[3] ^ wAB.y)
                       + __popc(Wd[4] ^ wAB.z) + __popc(Wd[5] ^ wAB.w)
                       + __popc(Wd[6] ^ wC.x)  + __popc(Wd[7] ^ wC.y);
                bool bit = (s0 <= K128) || (s1 <= K192);
                b3s[h * 64 + W] = __ballot_sync(0xffffffffu, bit);
            }
#pragma unroll
            for (int i = 0; i < 8; i++) Wd[i] = Wd[i + 4];

#pragma unroll
            for (int wp = 1; wp < 15; wp++) {
                uint4 p = *(const uint4*)(rp2 + 4 * wp + 6);
                Wd[8] = p.x; Wd[9] = p.y; Wd[10] = p.z; Wd[11] = p.w;
                int s0 = __popc(Wd[0] ^ wAB.x) + __popc(Wd[1] ^ wAB.y)
                       + __popc(Wd[2] ^ wAB.z) + __popc(Wd[3] ^ wAB.w)
                       + __popc(Wd[4] ^ wC.x)  + __popc(Wd[5] ^ wC.y);
                int s1 = __popc(Wd[2] ^ wAB.x) + __popc(Wd[3] ^ wAB.y)
                       + __popc(Wd[4] ^ wAB.z) + __popc(Wd[5] ^ wAB.w)
                       + __popc(Wd[6] ^ wC.x)  + __popc(Wd[7] ^ wC.y);
                bool bit = (s0 <= K192) || (s1 <= K192);
                b3s[h * 64 + wp * 4 + W] = __ballot_sync(0xffffffffu, bit);
#pragma unroll
                for (int i = 0; i < 8; i++) Wd[i] = Wd[i + 4];
            }
            {   // wp = 15 (s1: taps 0,1 -> K128)
                int s0 = __popc(Wd[0] ^ wAB.x) + __popc(Wd[1] ^ wAB.y)
                       + __popc(Wd[2] ^ wAB.z) + __popc(Wd[3] ^ wAB.w)
                       + __popc(Wd[4] ^ wC.x)  + __popc(Wd[5] ^ wC.y);
                int s1 = __popc(Wd[2] ^ wAB.x) + __popc(Wd[3] ^ wAB.y)
                       + __popc(Wd[4] ^ wAB.z) + __popc(Wd[5] ^ wAB.w);
                bool bit = (s0 <= K192) || (s1 <= K128);
                b3s[h * 64 + 60 + W] = __ballot_sync(0xffffffffu, bit);
            }
        }
    }
    __syncthreads();

    // ---- stage D: conv4 (128ch, cin 128, kh 6), coalesced transposed weights ----
    {
        int c = tid;
        int s[16];
#pragma unroll
        for (int w = 0; w < 16; w++) s[w] = 0;
#pragma unroll
        for (int h = 0; h < 6; h++) {
            const unsigned* wp4 = g_wb4t + (h * 4) * 128 + c;
            unsigned w0 = wp4[0], w1 = wp4[128], w2 = wp4[256], w3 = wp4[384];
#pragma unroll
            for (int w = 0; w < 16; w++) {
                uint4 A = *(const uint4*)&b3s[(h * 16 + w) * 4];
                s[w] += __popc(A.x ^ w0) + __popc(A.y ^ w1)
                      + __popc(A.z ^ w2) + __popc(A.w ^ w3);
            }
        }
        int K = g_kD[c];
        unsigned mask = 0;
#pragma unroll
        for (int w = 0; w < 16; w++)
            mask |= (s[w] <= K) ? (1u << w) : 0u;
        masks[c] = mask;
    }
    __syncthreads();

    // ---- stage E: fused repack + fc (10 x 2048 binary dot) + bf ----
    {
        uint2 mA = *(const uint2*)&masks[2 * L];
        uint2 mB = *(const uint2*)&masks[64 + 2 * L];
        unsigned f0 = mA.x | (mA.y << 16);
        unsigned f1 = mB.x | (mB.y << 16);
        for (int o = W; o < 10; o += 4) {
            int s = __popc(f0 ^ g_wfb[o * 64 + L])
                  + __popc(f1 ^ g_wfb[o * 64 + 32 + L]);
            int tot = __reduce_add_sync(0xffffffffu, s);
            if (L == 0) out[(size_t)b * 10 + o] = (float)(2048 - 2 * tot) + bf[o];
        }
    }
}

extern "C" void kernel_launch(void* const* d_in, const int* in_sizes, int n_in,
                              void* d_out, int out_size)
{
    const float* x   = (const float*)d_in[0];
    const float* w1  = (const float*)d_in[1];
    const float* b1  = (const float*)d_in[2];
    const float* w2  = (const float*)d_in[3];
    const float* b2  = (const float*)d_in[4];
    const float* w3  = (const float*)d_in[5];
    const float* b3  = (const float*)d_in[6];
    const float* w4  = (const float*)d_in[7];
    const float* b4  = (const float*)d_in[8];
    const float* g1  = (const float*)d_in[9];
    const float* be1 = (const float*)d_in[10];
    const float* m1  = (const float*)d_in[11];
    const float* v1  = (const float*)d_in[12];
    const float* g2  = (const float*)d_in[13];
    const float* be2 = (const float*)d_in[14];
    const float* m2  = (const float*)d_in[15];
    const float* v2  = (const float*)d_in[16];
    const float* g3  = (const float*)d_in[17];
    const float* be3 = (const float*)d_in[18];
    const float* m3  = (const float*)d_in[19];
    const float* v3  = (const float*)d_in[20];
    const float* g4  = (const float*)d_in[21];
    const float* be4 = (const float*)d_in[22];
    const float* m4  = (const float*)d_in[23];
    const float* v4  = (const float*)d_in[24];
    const float* wf  = (const float*)d_in[25];
    const float* bf  = (const float*)d_in[26];

    int B = in_sizes[0] / 768;

    prep_kernel<<<22, 256>>>(w1, b1, w2, b2, w3, b3, w4, b4,
                             g1, be1, m1, v1, g2, be2, m2, v2,
                             g3, be3, m3, v3, g4, be4, m4, v4, wf);
    bcnn_kernel<<<B, 128>>>(x, bf, (float*)d_out);
}